// round 3
// baseline (speedup 1.0000x reference)
#include <cuda_runtime.h>
#include <math.h>

// ---------------------------------------------------------------------------
// Problem constants
//   B=2, T=1024, D=384 -> d=128, D3=384, D9=1152, tokens NTOK=2048
//   GAMMA=5, EPS_W=1e-8, EPS_N=1e-5
// ---------------------------------------------------------------------------
#define NTOK 2048
#define D3   384
#define D9   1152
#define DD   128
#define NEG_GAMMA_LOG2E (-7.2134752044448169f)   // -GAMMA * log2(e)

// -------------------- device scratch (static, no allocs) -------------------
__device__ float g_SW  [3 * D3 * DD];       // softplus(Wq/Wk/Wv)   [g][m(384)][k(128)]
__device__ float g_Ft  [3 * DD * D3];       // fused S^T*SW, transposed: [g][k(128)][o(384)]
__device__ float g_fb  [3 * D3];            // fused bias S^T b
__device__ float g_Wpt [D3 * D9];           // softplus(Wp) transposed: [k(384)][o(1152)]
__device__ float g_QKV [NTOK * D9];         // per-token [Q(384) K(384) V(384)]
__device__ float g_att [NTOK * D3];
__device__ float g_h   [NTOK * D9];

// -------------------- helpers ----------------------------------------------
__device__ __forceinline__ float splus(float w) {
    // numerically stable softplus, matches jax.nn.softplus in fp32
    return fmaxf(w, 0.0f) + log1pf(expf(-fabsf(w)));
}
__device__ __forceinline__ float fast_ex2(float x) {
    float y; asm("ex2.approx.ftz.f32 %0, %1;" : "=f"(y) : "f"(x)); return y;
}
__device__ __forceinline__ float fast_rcp(float x) {
    float y; asm("rcp.approx.ftz.f32 %0, %1;" : "=f"(y) : "f"(x)); return y;
}

// -------------------- K0a: softplus of Wq/Wk/Wv -----------------------------
__global__ void k_softplus_qkv(const float* __restrict__ Wq,
                               const float* __restrict__ Wk,
                               const float* __restrict__ Wv) {
    int idx = blockIdx.x * blockDim.x + threadIdx.x;     // 3*384*128 = 147456
    if (idx >= 3 * D3 * DD) return;
    int g = idx / (D3 * DD);
    int r = idx - g * (D3 * DD);
    const float* W = (g == 0) ? Wq : (g == 1) ? Wk : Wv;
    g_SW[idx] = splus(W[r]);
}

// -------------------- K0b: softplus(Wp) transposed --------------------------
__global__ void k_softplus_wpt(const float* __restrict__ Wp) {
    int idx = blockIdx.x * blockDim.x + threadIdx.x;     // 384*1152 = 442368
    if (idx >= D3 * D9) return;
    int k = idx / D9;
    int o = idx - k * D9;
    g_Wpt[idx] = splus(Wp[o * D3 + k]);                  // Wp is [1152][384]
}

// -------------------- K0c: fold orthogonal S into weights -------------------
// Ft[g][k][o] = sum_m S_g[m][o] * SW_g[m][k]
__global__ void k_fuse(const float* __restrict__ Sq,
                       const float* __restrict__ Sk,
                       const float* __restrict__ Sv) {
    int idx = blockIdx.x * blockDim.x + threadIdx.x;     // 147456
    if (idx >= 3 * DD * D3) return;
    int g = idx / (DD * D3);
    int r = idx - g * (DD * D3);
    int k = r / D3;
    int o = r - k * D3;
    const float* S  = (g == 0) ? Sq : (g == 1) ? Sk : Sv;
    const float* sw = g_SW + g * (D3 * DD) + k;
    float acc = 0.0f;
#pragma unroll 4
    for (int m = 0; m < D3; m++)
        acc = fmaf(S[m * D3 + o], sw[m * DD], acc);
    g_Ft[idx] = acc;
}

// fb[g][o] = sum_m S_g[m][o] * b_g[m]
__global__ void k_fbias(const float* __restrict__ Sq, const float* __restrict__ Sk,
                        const float* __restrict__ Sv,
                        const float* __restrict__ bq, const float* __restrict__ bk,
                        const float* __restrict__ bv) {
    int idx = blockIdx.x * blockDim.x + threadIdx.x;     // 1152
    if (idx >= 3 * D3) return;
    int g = idx / D3;
    int o = idx - g * D3;
    const float* S = (g == 0) ? Sq : (g == 1) ? Sk : Sv;
    const float* b = (g == 0) ? bq : (g == 1) ? bk : bv;
    float acc = 0.0f;
#pragma unroll 4
    for (int m = 0; m < D3; m++)
        acc = fmaf(S[m * D3 + o], b[m], acc);
    g_fb[idx] = acc;
}

// -------------------- K1: fused QKV projection ------------------------------
// 16 tokens per CTA, 384 threads; thread 'o' produces Q[o],K[o],V[o] for all 16.
__global__ __launch_bounds__(384) void k_qkv(const float* __restrict__ x) {
    __shared__ float sx[D3][17];                          // [kk][m], pad -> no conflicts
    const int t0  = blockIdx.x * 16;
    const int tid = threadIdx.x;

#pragma unroll
    for (int m = 0; m < 16; m++)
        sx[tid][m] = x[(t0 + m) * D3 + tid];              // coalesced
    __syncthreads();

    float a0[16], a1[16], a2[16];
#pragma unroll
    for (int m = 0; m < 16; m++) { a0[m] = 0.f; a1[m] = 0.f; a2[m] = 0.f; }

    const float* F0 = g_Ft + 0 * (DD * D3) + tid;
    const float* F1 = g_Ft + 1 * (DD * D3) + tid;
    const float* F2 = g_Ft + 2 * (DD * D3) + tid;

#pragma unroll 2
    for (int k = 0; k < DD; k++) {
        float w0 = F0[k * D3];                            // coalesced over tid
        float w1 = F1[k * D3];
        float w2 = F2[k * D3];
#pragma unroll
        for (int m = 0; m < 16; m++) {
            a0[m] = fmaf(sx[k      ][m], w0, a0[m]);      // broadcast LDS
            a1[m] = fmaf(sx[128 + k][m], w1, a1[m]);
            a2[m] = fmaf(sx[256 + k][m], w2, a2[m]);
        }
    }
    const float b0 = g_fb[tid], b1 = g_fb[D3 + tid], b2 = g_fb[2 * D3 + tid];
#pragma unroll
    for (int m = 0; m < 16; m++) {
        float* q = g_QKV + (t0 + m) * D9;
        q[tid]            = a0[m] + b0;
        q[D3 + tid]       = a1[m] + b1;
        q[2 * D3 + tid]   = a2[m] + b2;
    }
}

// -------------------- K2: per-token sigmoid-outer attention -----------------
// att_i = (sum_j s_ij * v_j) / (sum_j s_ij + 1e-8),  s_ij = sigmoid(GAMMA*q_i*k_j)
// s_ij = 1 / (1 + 2^(q_i * c_j)),  c_j = -GAMMA*log2(e)*k_j
__global__ __launch_bounds__(384) void k_attn() {
    __shared__ float  sq[D3];
    __shared__ float2 scv[D3];
    const int t   = blockIdx.x;
    const int tid = threadIdx.x;
    const float* base = g_QKV + t * D9;

    sq[tid] = base[tid];
    {
        float kk = base[D3 + tid];
        float vv = base[2 * D3 + tid];
        scv[tid] = make_float2(kk * NEG_GAMMA_LOG2E, vv);
    }
    __syncthreads();

    const float qi = sq[tid];
    float num = 0.0f, den = 0.0f;
#pragma unroll 8
    for (int j = 0; j < D3; j++) {
        float2 cv = scv[j];                               // broadcast LDS.64
        float e = fast_ex2(qi * cv.x);                    // 2^(qi*cj) = exp(-g*q*k)
        float s = fast_rcp(1.0f + e);                     // sigmoid
        num = fmaf(s, cv.y, num);
        den += s;
    }
    g_att[t * D3 + tid] = num / (den + 1e-8f);
}

// -------------------- K3: h = att @ softplus(Wp)^T + bp ---------------------
__global__ __launch_bounds__(384) void k_gemm3(const float* __restrict__ bp) {
    __shared__ float sa[D3][17];
    const int t0  = blockIdx.x * 16;
    const int tid = threadIdx.x;

#pragma unroll
    for (int m = 0; m < 16; m++)
        sa[tid][m] = g_att[(t0 + m) * D3 + tid];
    __syncthreads();

    float a0[16], a1[16], a2[16];
#pragma unroll
    for (int m = 0; m < 16; m++) { a0[m] = 0.f; a1[m] = 0.f; a2[m] = 0.f; }

#pragma unroll 2
    for (int k = 0; k < D3; k++) {
        const float* w = g_Wpt + k * D9 + tid;
        float w0 = w[0];                                  // coalesced
        float w1 = w[D3];
        float w2 = w[2 * D3];
#pragma unroll
        for (int m = 0; m < 16; m++) {
            float a = sa[k][m];                           // broadcast
            a0[m] = fmaf(a, w0, a0[m]);
            a1[m] = fmaf(a, w1, a1[m]);
            a2[m] = fmaf(a, w2, a2[m]);
        }
    }
    const float b0 = bp[tid], b1 = bp[D3 + tid], b2 = bp[2 * D3 + tid];
#pragma unroll
    for (int m = 0; m < 16; m++) {
        float* h = g_h + (t0 + m) * D9;
        h[tid]          = a0[m] + b0;
        h[D3 + tid]     = a1[m] + b1;
        h[2 * D3 + tid] = a2[m] + b2;
    }
}

// -------------------- K4: LayerNorm over D9, two-pass -----------------------
__global__ __launch_bounds__(384) void k_ln(const float* __restrict__ gn,
                                            const float* __restrict__ bn,
                                            float* __restrict__ out) {
    const int t   = blockIdx.x;
    const int tid = threadIdx.x;
    const float* h = g_h + t * D9;

    float v0 = h[tid], v1 = h[D3 + tid], v2 = h[2 * D3 + tid];

    __shared__ float red[12];
    __shared__ float bc[2];
    const int lane = tid & 31, wid = tid >> 5;

    // pass 1: mean
    float s = v0 + v1 + v2;
#pragma unroll
    for (int o = 16; o > 0; o >>= 1) s += __shfl_down_sync(0xffffffffu, s, o);
    if (lane == 0) red[wid] = s;
    __syncthreads();
    if (tid == 0) {
        float tot = 0.f;
#pragma unroll
        for (int i = 0; i < 12; i++) tot += red[i];
        bc[0] = tot * (1.0f / 1152.0f);
    }
    __syncthreads();
    const float mu = bc[0];

    // pass 2: variance (two-pass avoids E[x^2]-mu^2 cancellation)
    float d0 = v0 - mu, d1 = v1 - mu, d2 = v2 - mu;
    float ss = d0 * d0 + d1 * d1 + d2 * d2;
#pragma unroll
    for (int o = 16; o > 0; o >>= 1) ss += __shfl_down_sync(0xffffffffu, ss, o);
    __syncthreads();   // ensure red[] reads from pass 1 are done
    if (lane == 0) red[wid] = ss;
    __syncthreads();
    if (tid == 0) {
        float tot = 0.f;
#pragma unroll
        for (int i = 0; i < 12; i++) tot += red[i];
        bc[1] = rsqrtf(tot * (1.0f / 1152.0f) + 1e-5f);
    }
    __syncthreads();
    const float rs = bc[1];

    float* o = out + t * D9;
    o[tid]          = d0 * rs * gn[tid]          + bn[tid];
    o[D3 + tid]     = d1 * rs * gn[D3 + tid]     + bn[D3 + tid];
    o[2 * D3 + tid] = d2 * rs * gn[2 * D3 + tid] + bn[2 * D3 + tid];
}

// -------------------- launch -------------------------------------------------
extern "C" void kernel_launch(void* const* d_in, const int* in_sizes, int n_in,
                              void* d_out, int out_size) {
    const float* x  = (const float*)d_in[0];
    const float* Wq = (const float*)d_in[1];
    const float* bq = (const float*)d_in[2];
    const float* Sq = (const float*)d_in[3];
    const float* Wk = (const float*)d_in[4];
    const float* bk = (const float*)d_in[5];
    const float* Sk = (const float*)d_in[6];
    const float* Wv = (const float*)d_in[7];
    const float* bv = (const float*)d_in[8];
    const float* Sv = (const float*)d_in[9];
    const float* Wp = (const float*)d_in[10];
    const float* bp = (const float*)d_in[11];
    const float* gn = (const float*)d_in[12];
    const float* bn = (const float*)d_in[13];
    float* out = (float*)d_out;

    k_softplus_qkv<<<(3 * D3 * DD + 255) / 256, 256>>>(Wq, Wk, Wv);
    k_softplus_wpt<<<(D3 * D9 + 255) / 256, 256>>>(Wp);
    k_fuse <<<(3 * DD * D3 + 255) / 256, 256>>>(Sq, Sk, Sv);
    k_fbias<<<(3 * D3 + 255) / 256, 256>>>(Sq, Sk, Sv, bq, bk, bv);

    k_qkv  <<<NTOK / 16, 384>>>(x);
    k_attn <<<NTOK, 384>>>();
    k_gemm3<<<NTOK / 16, 384>>>(bp);
    k_ln   <<<NTOK, 384>>>(gn, bn, out);
}

// round 4
// speedup vs baseline: 1.5961x; 1.5961x over previous
#include <cuda_runtime.h>
#include <math.h>

// ---------------------------------------------------------------------------
//   B=2, T=1024, D=384 -> d=128, D3=384, D9=1152, NTOK=2048
//   GAMMA=5, EPS_W=1e-8, EPS_N=1e-5
// ---------------------------------------------------------------------------
#define NTOK 2048
#define D3   384
#define D9   1152
#define DD   128
#define HALF_GAMMA 2.5f

// -------------------- device scratch (static, no allocs) -------------------
__device__ float g_Ft  [3 * DD * D3];       // fused softplus(W)^T * S: [g][k(128)][o(384)]
__device__ float g_fb  [3 * D3];            // fused bias  S^T b
__device__ float g_Wpt [D3 * D9];           // softplus(Wp) transposed: [k(384)][o(1152)]
__device__ float g_QKV [NTOK * D9];         // per-token [Q(384) K(384) V(384)]
__device__ float g_att [NTOK * D3];

// -------------------- helpers ----------------------------------------------
__device__ __forceinline__ float sp_fast(float w) {
    // softplus; inputs here are ~N(0,0.05): exp(-|w|) in [0.74,1], no cancellation
    return fmaxf(w, 0.0f) + __logf(1.0f + __expf(-fabsf(w)));
}
__device__ __forceinline__ float fast_tanh(float x) {
    float y; asm("tanh.approx.f32 %0, %1;" : "=f"(y) : "f"(x)); return y;
}

#define LOAD16(dst, rowptr) do {                                              \
    const float4* _r = (const float4*)(rowptr);                               \
    float4 _q0 = _r[0], _q1 = _r[1], _q2 = _r[2], _q3 = _r[3];                \
    dst[0]=_q0.x;  dst[1]=_q0.y;  dst[2]=_q0.z;  dst[3]=_q0.w;                \
    dst[4]=_q1.x;  dst[5]=_q1.y;  dst[6]=_q1.z;  dst[7]=_q1.w;                \
    dst[8]=_q2.x;  dst[9]=_q2.y;  dst[10]=_q2.z; dst[11]=_q2.w;               \
    dst[12]=_q3.x; dst[13]=_q3.y; dst[14]=_q3.z; dst[15]=_q3.w;               \
} while (0)

// -------------------- K0a: fused softplus+mix  Ft[g][k][o] ------------------
// Ft[k][o] = sum_m softplus(W[m][k]) * S[m][o]
// grid (32, 3): each block = one g, 4 consecutive k values, all 384 o.
__global__ __launch_bounds__(384) void k_fuse(
        const float* __restrict__ Wq, const float* __restrict__ Wk,
        const float* __restrict__ Wv,
        const float* __restrict__ Sq, const float* __restrict__ Sk,
        const float* __restrict__ Sv) {
    __shared__ float4 ssw[D3];
    const int g  = blockIdx.y;
    const int k0 = blockIdx.x * 4;
    const int tid = threadIdx.x;
    const float* W = (g == 0) ? Wq : (g == 1) ? Wk : Wv;
    const float* S = (g == 0) ? Sq : (g == 1) ? Sk : Sv;

    float4 w = *(const float4*)(W + tid * DD + k0);
    w.x = sp_fast(w.x); w.y = sp_fast(w.y); w.z = sp_fast(w.z); w.w = sp_fast(w.w);
    ssw[tid] = w;
    __syncthreads();

    float4 acc = make_float4(0.f, 0.f, 0.f, 0.f);
#pragma unroll 4
    for (int m = 0; m < D3; m++) {
        float s  = S[m * D3 + tid];                  // coalesced LDG
        float4 c = ssw[m];                           // LDS.128 broadcast
        acc.x = fmaf(s, c.x, acc.x);
        acc.y = fmaf(s, c.y, acc.y);
        acc.z = fmaf(s, c.z, acc.z);
        acc.w = fmaf(s, c.w, acc.w);
    }
    float* dst = g_Ft + g * (DD * D3) + k0 * D3 + tid;
    dst[0]      = acc.x;
    dst[D3]     = acc.y;
    dst[2 * D3] = acc.z;
    dst[3 * D3] = acc.w;
}

// -------------------- K0b: fused bias fb[g][o] = sum_m S[m][o]*b[m] ---------
// one warp per output (1152 warps).
__global__ void k_fbias(const float* __restrict__ Sq, const float* __restrict__ Sk,
                        const float* __restrict__ Sv,
                        const float* __restrict__ bq, const float* __restrict__ bk,
                        const float* __restrict__ bv) {
    const int w    = (blockIdx.x * blockDim.x + threadIdx.x) >> 5;
    const int lane = threadIdx.x & 31;
    if (w >= 3 * D3) return;
    const int g = w / D3, o = w - g * D3;
    const float* S = (g == 0) ? Sq : (g == 1) ? Sk : Sv;
    const float* b = (g == 0) ? bq : (g == 1) ? bk : bv;
    float acc = 0.0f;
#pragma unroll
    for (int i = 0; i < 12; i++) {
        int m = lane + i * 32;
        acc = fmaf(S[m * D3 + o], b[m], acc);
    }
#pragma unroll
    for (int off = 16; off > 0; off >>= 1)
        acc += __shfl_down_sync(0xffffffffu, acc, off);
    if (lane == 0) g_fb[w] = acc;
}

// -------------------- K0c: softplus(Wp) transposed via smem tiles -----------
__global__ void k_wpt(const float* __restrict__ Wp) {
    __shared__ float tile[32][33];
    const int k0 = blockIdx.x * 32;                  // 384/32 = 12
    const int o0 = blockIdx.y * 32;                  // 1152/32 = 36
    const int tx = threadIdx.x, ty = threadIdx.y;    // 32 x 8
#pragma unroll
    for (int i = 0; i < 32; i += 8)
        tile[ty + i][tx] = Wp[(o0 + ty + i) * D3 + k0 + tx];   // coalesced over k
    __syncthreads();
#pragma unroll
    for (int i = 0; i < 32; i += 8)
        g_Wpt[(k0 + ty + i) * D9 + o0 + tx] = sp_fast(tile[tx][ty + i]); // coalesced over o
}

// -------------------- K1: QKV projection (16 tokens/CTA) --------------------
__global__ __launch_bounds__(384) void k_qkv(const float* __restrict__ x) {
    __shared__ float sx[D3][20];                     // 80B rows: 16B-aligned, 4-way wr conflict
    const int t0  = blockIdx.x * 16;
    const int tid = threadIdx.x;

#pragma unroll
    for (int m = 0; m < 16; m++)
        sx[tid][m] = x[(t0 + m) * D3 + tid];
    __syncthreads();

    float a0[16], a1[16], a2[16];
#pragma unroll
    for (int m = 0; m < 16; m++) { a0[m] = 0.f; a1[m] = 0.f; a2[m] = 0.f; }

    const float* F0 = g_Ft + 0 * (DD * D3) + tid;
    const float* F1 = g_Ft + 1 * (DD * D3) + tid;
    const float* F2 = g_Ft + 2 * (DD * D3) + tid;

    float xv[16];
#pragma unroll 2
    for (int k = 0; k < DD; k++) {
        float w0 = F0[k * D3];
        float w1 = F1[k * D3];
        float w2 = F2[k * D3];
        LOAD16(xv, &sx[k][0]);
#pragma unroll
        for (int m = 0; m < 16; m++) a0[m] = fmaf(xv[m], w0, a0[m]);
        LOAD16(xv, &sx[128 + k][0]);
#pragma unroll
        for (int m = 0; m < 16; m++) a1[m] = fmaf(xv[m], w1, a1[m]);
        LOAD16(xv, &sx[256 + k][0]);
#pragma unroll
        for (int m = 0; m < 16; m++) a2[m] = fmaf(xv[m], w2, a2[m]);
    }
    const float b0 = g_fb[tid], b1 = g_fb[D3 + tid], b2 = g_fb[2 * D3 + tid];
#pragma unroll
    for (int m = 0; m < 16; m++) {
        float* q = g_QKV + (t0 + m) * D9;
        q[tid]          = a0[m] + b0;
        q[D3 + tid]     = a1[m] + b1;
        q[2 * D3 + tid] = a2[m] + b2;
    }
}

// -------------------- K2: sigmoid-outer attention (tanh form) ---------------
// s_ij = sigmoid(g*q_i*k_j) = 0.5 + 0.5*tanh(0.5*g*q_i*k_j)
// att_i = (0.5*sum_j t_ij v_j + 0.5*sumV) / (0.5*sum_j t_ij + 192 + 1e-8)
__global__ __launch_bounds__(384) void k_attn() {
    __shared__ float2 scv[D3];
    __shared__ float  red[12];
    __shared__ float  s_sumv;
    const int t   = blockIdx.x;
    const int tid = threadIdx.x;
    const int lane = tid & 31, wid = tid >> 5;
    const float* base = g_QKV + t * D9;

    const float qi = base[tid];
    const float vv = base[2 * D3 + tid];
    scv[tid] = make_float2(base[D3 + tid] * HALF_GAMMA, vv);

    float sv = vv;
#pragma unroll
    for (int off = 16; off > 0; off >>= 1)
        sv += __shfl_down_sync(0xffffffffu, sv, off);
    if (lane == 0) red[wid] = sv;
    __syncthreads();
    if (tid == 0) {
        float tot = 0.f;
#pragma unroll
        for (int i = 0; i < 12; i++) tot += red[i];
        s_sumv = tot;
    }
    __syncthreads();

    float tv = 0.0f, ts = 0.0f;
#pragma unroll 8
    for (int j = 0; j < D3; j++) {
        float2 cv = scv[j];                          // LDS.64 broadcast
        float th  = fast_tanh(qi * cv.x);            // 1 MUFU op
        tv = fmaf(th, cv.y, tv);
        ts += th;
    }
    float num = fmaf(0.5f, tv, 0.5f * s_sumv);
    float den = fmaf(0.5f, ts, 192.0f + 1e-8f);
    g_att[t * D3 + tid] = num / den;
}

// -------------------- K3: h = att @ softplus(Wp)^T + bp, fused LayerNorm ----
__global__ __launch_bounds__(384) void k_gemm3ln(const float* __restrict__ bp,
                                                 const float* __restrict__ gn,
                                                 const float* __restrict__ bn,
                                                 float* __restrict__ out) {
    __shared__ float sa[D3][20];
    __shared__ float red[16][13];
    __shared__ float smu[16], srs[16];
    const int t0  = blockIdx.x * 16;
    const int tid = threadIdx.x;
    const int lane = tid & 31, wid = tid >> 5;

#pragma unroll
    for (int m = 0; m < 16; m++)
        sa[tid][m] = g_att[(t0 + m) * D3 + tid];
    __syncthreads();

    float a0[16], a1[16], a2[16];
#pragma unroll
    for (int m = 0; m < 16; m++) { a0[m] = 0.f; a1[m] = 0.f; a2[m] = 0.f; }

    float xv[16];
#pragma unroll 2
    for (int k = 0; k < D3; k++) {
        const float* w = g_Wpt + k * D9 + tid;
        float w0 = w[0];
        float w1 = w[D3];
        float w2 = w[2 * D3];
        LOAD16(xv, &sa[k][0]);
#pragma unroll
        for (int m = 0; m < 16; m++) {
            a0[m] = fmaf(xv[m], w0, a0[m]);
            a1[m] = fmaf(xv[m], w1, a1[m]);
            a2[m] = fmaf(xv[m], w2, a2[m]);
        }
    }
    const float b0 = bp[tid], b1 = bp[D3 + tid], b2 = bp[2 * D3 + tid];
#pragma unroll
    for (int m = 0; m < 16; m++) { a0[m] += b0; a1[m] += b1; a2[m] += b2; }

    // ---- mean ----
#pragma unroll
    for (int m = 0; m < 16; m++) {
        float s = a0[m] + a1[m] + a2[m];
#pragma unroll
        for (int off = 16; off > 0; off >>= 1)
            s += __shfl_down_sync(0xffffffffu, s, off);
        if (lane == 0) red[m][wid] = s;
    }
    __syncthreads();
    if (tid < 16) {
        float tot = 0.f;
#pragma unroll
        for (int i = 0; i < 12; i++) tot += red[tid][i];
        smu[tid] = tot * (1.0f / 1152.0f);
    }
    __syncthreads();

    // ---- variance (two-pass for conditioning) ----
#pragma unroll
    for (int m = 0; m < 16; m++) {
        float mu = smu[m];
        float d0 = a0[m] - mu, d1 = a1[m] - mu, d2 = a2[m] - mu;
        float s = d0 * d0 + d1 * d1 + d2 * d2;
#pragma unroll
        for (int off = 16; off > 0; off >>= 1)
            s += __shfl_down_sync(0xffffffffu, s, off);
        if (lane == 0) red[m][wid] = s;
    }
    __syncthreads();
    if (tid < 16) {
        float tot = 0.f;
#pragma unroll
        for (int i = 0; i < 12; i++) tot += red[tid][i];
        srs[tid] = rsqrtf(tot * (1.0f / 1152.0f) + 1e-5f);
    }
    __syncthreads();

    const float g0 = gn[tid], g1 = gn[D3 + tid], g2 = gn[2 * D3 + tid];
    const float n0 = bn[tid], n1 = bn[D3 + tid], n2 = bn[2 * D3 + tid];
#pragma unroll
    for (int m = 0; m < 16; m++) {
        float mu = smu[m], rs = srs[m];
        float* o = out + (t0 + m) * D9;
        o[tid]          = (a0[m] - mu) * rs * g0 + n0;
        o[D3 + tid]     = (a1[m] - mu) * rs * g1 + n1;
        o[2 * D3 + tid] = (a2[m] - mu) * rs * g2 + n2;
    }
}

// -------------------- launch -------------------------------------------------
extern "C" void kernel_launch(void* const* d_in, const int* in_sizes, int n_in,
                              void* d_out, int out_size) {
    const float* x  = (const float*)d_in[0];
    const float* Wq = (const float*)d_in[1];
    const float* bq = (const float*)d_in[2];
    const float* Sq = (const float*)d_in[3];
    const float* Wk = (const float*)d_in[4];
    const float* bk = (const float*)d_in[5];
    const float* Sk = (const float*)d_in[6];
    const float* Wv = (const float*)d_in[7];
    const float* bv = (const float*)d_in[8];
    const float* Sv = (const float*)d_in[9];
    const float* Wp = (const float*)d_in[10];
    const float* bp = (const float*)d_in[11];
    const float* gn = (const float*)d_in[12];
    const float* bn = (const float*)d_in[13];
    float* out = (float*)d_out;

    k_fuse  <<<dim3(32, 3), 384>>>(Wq, Wk, Wv, Sq, Sk, Sv);
    k_fbias <<<144, 256>>>(Sq, Sk, Sv, bq, bk, bv);
    k_wpt   <<<dim3(12, 36), dim3(32, 8)>>>(Wp);
    k_qkv   <<<NTOK / 16, 384>>>(x);
    k_attn  <<<NTOK, 384>>>();
    k_gemm3ln<<<NTOK / 16, 384>>>(bp, gn, bn, out);
}